// round 5
// baseline (speedup 1.0000x reference)
#include <cuda_runtime.h>
#include <cstdint>
#include <math.h>

#define STAGES 4
#define NTHREADS 256
// CTA tile 128x256, BK=32, padded K-pitch 36 words
#define ASZ (128 * 36)
#define BSZ (256 * 36)
#define SMEM_BYTES ((STAGES * (ASZ + BSZ)) * 4)   // 221184

// ---------------- scratch ----------------------------------------------------
__device__ float g_concat[(size_t)4096 * 7168];   // rounded concat
__device__ float g_Wch2[(size_t)2048 * 7168];
__device__ float g_Wcm2[(size_t)100 * 7168];
__device__ float g_Wmo[(size_t)256 * 128];        // padded ld=128, cols>=100 zero
__device__ float g_Wci[(size_t)2048 * 1024];
__device__ float g_Wch[(size_t)2048 * 2048];
__device__ float g_Wfc[(size_t)2048 * 2048];
__device__ float g_nhr[(size_t)4096 * 2048];      // rounded new_hidden
__device__ float g_lcr[(size_t)4096 * 2048];      // rounded lc
__device__ float g_midp[(size_t)4 * 4096 * 256];  // split-K partials for mid
__device__ float g_midr[(size_t)4096 * 128];      // rounded relu(mid), padded

// ---------------- helpers ----------------------------------------------------
__device__ __forceinline__ float rna(float x) {
  uint32_t r;
  asm("cvt.rna.tf32.f32 %0, %1;" : "=r"(r) : "f"(x));
  return __uint_as_float(r);
}
__device__ __forceinline__ void cpasync16(uint32_t saddr, const void* g, int sz) {
  asm volatile("cp.async.cg.shared.global [%0], [%1], 16, %2;\n"
               :: "r"(saddr), "l"(g), "r"(sz));
}
#define CP_COMMIT() asm volatile("cp.async.commit_group;\n" ::: "memory")

// ---------------- preprocessing ----------------------------------------------
__global__ void rna1d(float* __restrict__ dst, const float* __restrict__ src, int n4) {
  int stride = gridDim.x * blockDim.x;
  int i0 = blockIdx.x * blockDim.x + threadIdx.x;
  for (int i = i0; i < n4; i += 4 * stride) {
#pragma unroll
    for (int j = 0; j < 4; j++) {
      int k = i + j * stride;
      if (k < n4) {
        float4 v = ((const float4*)src)[k];
        v.x = rna(v.x); v.y = rna(v.y); v.z = rna(v.z); v.w = rna(v.w);
        ((float4*)dst)[k] = v;
      }
    }
  }
}
// Rounded strided copy: writes rows x dcols into dst with row pitch dpitch.
// cols [0,scols) copied+rounded from src (pitch spitch); cols [scols,dcols)
// written as zero. dcols and scols are multiples of 4; dcols <= dpitch.
__global__ void rna2d(float* __restrict__ dst, int dpitch,
                      const float* __restrict__ src, int spitch,
                      int rows, int scols, int dcols) {
  int dc4 = dcols >> 2;
  int total = rows * dc4;
  int stride = gridDim.x * blockDim.x;
  int i0 = blockIdx.x * blockDim.x + threadIdx.x;
  for (int i = i0; i < total; i += 4 * stride) {
#pragma unroll
    for (int j = 0; j < 4; j++) {
      int k = i + j * stride;
      if (k < total) {
        int r = k / dc4, c = (k - r * dc4) << 2;
        float4 v = make_float4(0.f, 0.f, 0.f, 0.f);
        if (c < scols) {
          v = *(const float4*)(src + (size_t)r * spitch + c);
          v.x = rna(v.x); v.y = rna(v.y); v.z = rna(v.z); v.w = rna(v.w);
        }
        *(float4*)(dst + (size_t)r * dpitch + c) = v;
      }
    }
  }
}
// sum 4 split-K partials (ld 256) + bias, relu, round -> g_midr [4096,128]
__global__ void reduce_mid(const float* __restrict__ part,
                           const float* __restrict__ bias,
                           float* __restrict__ outr) {
  int i = blockIdx.x * blockDim.x + threadIdx.x;
  if (i >= 4096 * 128) return;
  int r = i >> 7, c = i & 127;
  float v = 0.f;
  if (c < 100) {
    float s = bias[c];
#pragma unroll
    for (int z = 0; z < 4; z++)
      s += part[(size_t)z * 4096 * 256 + (size_t)r * 256 + c];
    v = rna(fmaxf(s, 0.f));
  }
  outr[(size_t)r * 128 + c] = v;
}

// ---------------- main GEMM --------------------------------------------------
struct GP {
  int M, N, Ktot;
  int lda, ldb;
  const float* A;
  const float* B;
  const float* bias1;
  const float* bias2;
  const float* addC; int addld;
  float* C1; int ldc1;
  float* C2; int ldc2;
  int act;                 // 0 none, 2 tanh
  int nkt;                 // k-tiles per z-slice
  int partial;             // 1: raw partials at C1 + z*partStride, ld 256
  long long partStride;
};

__global__ __launch_bounds__(NTHREADS, 1)
void gemm_k(GP p) {
  extern __shared__ float sm[];
  float* As = sm;
  float* Bs = sm + (size_t)STAGES * ASZ;
  uint32_t sA = (uint32_t)__cvta_generic_to_shared(As);
  uint32_t sB = (uint32_t)__cvta_generic_to_shared(Bs);

  const int tid  = threadIdx.x;
  const int lane = tid & 31;
  const int warp = tid >> 5;
  const int wm   = warp >> 2;    // 0..1 -> 64-row slice of 128
  const int wn   = warp & 3;     // 0..3 -> 64-col slice of 256
  const int gid  = lane >> 2;
  const int tig  = lane & 3;

  const int m0 = blockIdx.y * 128;
  const int n0 = blockIdx.x * 256;
  const int z  = blockIdx.z;
  const int kt0 = z * p.nkt;

  float acc[4][8][4];
#pragma unroll
  for (int a = 0; a < 4; a++)
#pragma unroll
    for (int b = 0; b < 8; b++)
#pragma unroll
      for (int c = 0; c < 4; c++) acc[a][b][c] = 0.f;

  auto issue = [&](int kti) {
    int buf = kti & (STAGES - 1);
    int k0 = (kt0 + kti) * 32;
    uint32_t da = sA + buf * (ASZ * 4);
    uint32_t db = sB + buf * (BSZ * 4);
#pragma unroll
    for (int i = 0; i < 4; i++) {
      int idx = tid + i * NTHREADS;
      int row = idx >> 3;
      int c4  = (idx & 7) << 2;
      const float* g = p.A + (size_t)(m0 + row) * p.lda + k0 + c4;
      int sz = (k0 + c4 < p.Ktot) ? 16 : 0;
      cpasync16(da + (uint32_t)(row * 36 + c4) * 4, g, sz);
    }
#pragma unroll
    for (int i = 0; i < 8; i++) {
      int idx = tid + i * NTHREADS;
      int row = idx >> 3;
      int c4  = (idx & 7) << 2;
      const float* g = p.B + (size_t)(n0 + row) * p.ldb + k0 + c4;
      int sz = ((k0 + c4 < p.Ktot) && (n0 + row < p.N)) ? 16 : 0;
      cpasync16(db + (uint32_t)(row * 36 + c4) * 4, g, sz);
    }
  };

  const int nkt = p.nkt;
#pragma unroll
  for (int s = 0; s < STAGES - 1; s++) {
    if (s < nkt) issue(s);
    CP_COMMIT();
  }

  for (int kt = 0; kt < nkt; kt++) {
    asm volatile("cp.async.wait_group %0;\n" :: "n"(STAGES - 2) : "memory");
    __syncthreads();
    if (kt + STAGES - 1 < nkt) issue(kt + STAGES - 1);
    CP_COMMIT();

    int buf = kt & (STAGES - 1);
    const uint32_t* a = (const uint32_t*)(As + (size_t)buf * ASZ);
    const uint32_t* b = (const uint32_t*)(Bs + (size_t)buf * BSZ);
#pragma unroll
    for (int ks = 0; ks < 4; ks++) {
      uint32_t af[4][4], bf[8][2];
      const int c = ks * 8 + tig;
#pragma unroll
      for (int tm = 0; tm < 4; tm++) {
        int r = wm * 64 + tm * 16 + gid;
        af[tm][0] = a[r * 36 + c];
        af[tm][1] = a[(r + 8) * 36 + c];
        af[tm][2] = a[r * 36 + c + 4];
        af[tm][3] = a[(r + 8) * 36 + c + 4];
      }
#pragma unroll
      for (int tn = 0; tn < 8; tn++) {
        int n = wn * 64 + tn * 8 + gid;
        bf[tn][0] = b[n * 36 + c];
        bf[tn][1] = b[n * 36 + c + 4];
      }
#pragma unroll
      for (int tm = 0; tm < 4; tm++)
#pragma unroll
        for (int tn = 0; tn < 8; tn++) {
          asm volatile(
              "mma.sync.aligned.m16n8k8.row.col.f32.tf32.tf32.f32 "
              "{%0,%1,%2,%3}, {%4,%5,%6,%7}, {%8,%9}, {%0,%1,%2,%3};\n"
              : "+f"(acc[tm][tn][0]), "+f"(acc[tm][tn][1]),
                "+f"(acc[tm][tn][2]), "+f"(acc[tm][tn][3])
              : "r"(af[tm][0]), "r"(af[tm][1]), "r"(af[tm][2]), "r"(af[tm][3]),
                "r"(bf[tn][0]), "r"(bf[tn][1]));
        }
    }
  }

  // ---- epilogue ----
  if (p.partial) {
    float* cbase = p.C1 + (size_t)z * p.partStride;
#pragma unroll
    for (int tm = 0; tm < 4; tm++) {
      int r0 = m0 + wm * 64 + tm * 16 + gid;
#pragma unroll
      for (int tn = 0; tn < 8; tn++) {
        int c0 = n0 + wn * 64 + tn * 8 + 2 * tig;
#pragma unroll
        for (int h = 0; h < 2; h++) {
          float2 v = make_float2(acc[tm][tn][h * 2], acc[tm][tn][h * 2 + 1]);
          *(float2*)(cbase + (size_t)(r0 + h * 8) * 256 + c0) = v;
        }
      }
    }
    return;
  }

#pragma unroll
  for (int tn = 0; tn < 8; tn++) {
    int c0 = n0 + wn * 64 + tn * 8 + 2 * tig;
    if (c0 >= p.N) continue;
    float b0 = p.bias1[c0], b1 = p.bias1[c0 + 1];
    if (p.bias2) { b0 += p.bias2[c0]; b1 += p.bias2[c0 + 1]; }
#pragma unroll
    for (int tm = 0; tm < 4; tm++) {
      int r0 = m0 + wm * 64 + tm * 16 + gid;
#pragma unroll
      for (int h = 0; h < 2; h++) {
        int r = r0 + h * 8;
        float vx = acc[tm][tn][h * 2] + b0;
        float vy = acc[tm][tn][h * 2 + 1] + b1;
        if (p.addC) {
          float2 ad = *(const float2*)(p.addC + (size_t)r * p.addld + c0);
          vx += ad.x; vy += ad.y;
        }
        if (p.act == 2) { vx = tanhf(vx); vy = tanhf(vy); }
        if (p.C1)
          *(float2*)(p.C1 + (size_t)r * p.ldc1 + c0) = make_float2(vx, vy);
        if (p.C2)
          *(float2*)(p.C2 + (size_t)r * p.ldc2 + c0) =
              make_float2(rna(vx), rna(vy));
      }
    }
  }
}

// ---------------- host --------------------------------------------------------
static void launch_gemm(const GP& p, int gx, int gy, int gz) {
  dim3 grid(gx, gy, gz);
  gemm_k<<<grid, NTHREADS, SMEM_BYTES>>>(p);
}

extern "C" void kernel_launch(void* const* d_in, const int* in_sizes, int n_in,
                              void* d_out, int out_size) {
  (void)in_sizes; (void)n_in; (void)out_size;
  const float* input  = (const float*)d_in[0];
  const float* hidden = (const float*)d_in[1];
  const float* prevh  = (const float*)d_in[2];
  const float* cell   = (const float*)d_in[3];
  const float* W_ch2  = (const float*)d_in[4];
  const float* b_ch2  = (const float*)d_in[5];
  const float* W_cm2  = (const float*)d_in[6];
  const float* b_cm2  = (const float*)d_in[7];
  const float* W_mo   = (const float*)d_in[8];
  const float* b_mo   = (const float*)d_in[9];
  const float* W_ci   = (const float*)d_in[10];
  const float* b_ci   = (const float*)d_in[11];
  const float* W_ch   = (const float*)d_in[12];
  const float* b_ch   = (const float*)d_in[13];
  const float* W_fc   = (const float*)d_in[14];
  const float* b_fc   = (const float*)d_in[15];
  const float* bias   = (const float*)d_in[16];

  float* out_p = (float*)d_out;                 // [4096,256]
  float* nh_p  = out_p + (size_t)4096 * 256;    // new_hidden
  float* nc_p  = nh_p + (size_t)4096 * 2048;    // new_cell
  float* nph_p = nc_p + (size_t)4096 * 2048;    // new_prev_hidden (= h_proj)

  float *concat_p, *Wch2_p, *Wcm2_p, *Wmo_p, *Wci_p, *Wch_p, *Wfc_p;
  float *nhr_p, *lcr_p, *midp_p, *midr_p;
  cudaGetSymbolAddress((void**)&concat_p, g_concat);
  cudaGetSymbolAddress((void**)&Wch2_p, g_Wch2);
  cudaGetSymbolAddress((void**)&Wcm2_p, g_Wcm2);
  cudaGetSymbolAddress((void**)&Wmo_p, g_Wmo);
  cudaGetSymbolAddress((void**)&Wci_p, g_Wci);
  cudaGetSymbolAddress((void**)&Wch_p, g_Wch);
  cudaGetSymbolAddress((void**)&Wfc_p, g_Wfc);
  cudaGetSymbolAddress((void**)&nhr_p, g_nhr);
  cudaGetSymbolAddress((void**)&lcr_p, g_lcr);
  cudaGetSymbolAddress((void**)&midp_p, g_midp);
  cudaGetSymbolAddress((void**)&midr_p, g_midr);

  cudaFuncSetAttribute(gemm_k, cudaFuncAttributeMaxDynamicSharedMemorySize,
                       SMEM_BYTES);

  // ---- preprocessing: RNA rounding ----
  auto r1 = [&](float* dst, const float* src, size_t n) {
    rna1d<<<1184, 256>>>(dst, src, (int)(n >> 2));
  };
  r1(Wch2_p, W_ch2, (size_t)2048 * 7168);
  r1(Wcm2_p, W_cm2, (size_t)100 * 7168);
  r1(Wci_p, W_ci, (size_t)2048 * 1024);
  r1(Wch_p, W_ch, (size_t)2048 * 2048);
  r1(Wfc_p, W_fc, (size_t)2048 * 2048);
  // Wmo: copy 256x100, zero-pad to 128 cols (pitch 128)
  rna2d<<<256, 256>>>(Wmo_p, 128, W_mo, 100, 256, 100, 128);
  // concat segments: pure strided copies (dcols == scols, no fill)
  rna2d<<<1184, 256>>>(concat_p,        7168, input,  1024, 4096, 1024, 1024);
  rna2d<<<1184, 256>>>(concat_p + 1024, 7168, hidden, 2048, 4096, 2048, 2048);
  rna2d<<<1184, 256>>>(concat_p + 3072, 7168, prevh,  2048, 4096, 2048, 2048);
  rna2d<<<1184, 256>>>(concat_p + 5120, 7168, cell,   2048, 4096, 2048, 2048);

  // 1) new_hidden = concat @ W_ch2^T + b_ch2   (exact->nh, rounded->nhr)
  {
    GP p{};
    p.M = 4096; p.N = 2048; p.Ktot = 7168; p.lda = 7168; p.ldb = 7168;
    p.A = concat_p; p.B = Wch2_p; p.bias1 = b_ch2;
    p.C1 = nh_p; p.ldc1 = 2048; p.C2 = nhr_p; p.ldc2 = 2048;
    p.nkt = 224;
    launch_gemm(p, 8, 32, 1);
  }
  // 2) mid partials = concat @ W_cm2^T  (split-K x4)
  {
    GP p{};
    p.M = 4096; p.N = 100; p.Ktot = 7168; p.lda = 7168; p.ldb = 7168;
    p.A = concat_p; p.B = Wcm2_p;
    p.C1 = midp_p; p.partial = 1; p.partStride = (long long)4096 * 256;
    p.nkt = 56;  // 56*32*4 = 7168
    launch_gemm(p, 1, 32, 4);
  }
  reduce_mid<<<(4096 * 128 + 255) / 256, 256>>>(midp_p, b_cm2, midr_p);
  // 3) out = mid @ W_mo^T + b_mo  (K padded to 128 with zeros)
  {
    GP p{};
    p.M = 4096; p.N = 256; p.Ktot = 128; p.lda = 128; p.ldb = 128;
    p.A = midr_p; p.B = Wmo_p; p.bias1 = b_mo;
    p.C1 = out_p; p.ldc1 = 256;
    p.nkt = 4;
    launch_gemm(p, 1, 32, 1);
  }
  // 4) h_proj = new_hidden @ W_ch^T + b_ch  -> new_prev_hidden (exact)
  {
    GP p{};
    p.M = 4096; p.N = 2048; p.Ktot = 2048; p.lda = 2048; p.ldb = 2048;
    p.A = nhr_p; p.B = Wch_p; p.bias1 = b_ch;
    p.C1 = nph_p; p.ldc1 = 2048;
    p.nkt = 64;
    launch_gemm(p, 8, 32, 1);
  }
  // 5) lc = input @ W_ci^T + b_ci + bias + h_proj   (rounded -> g_lcr)
  {
    GP p{};
    p.M = 4096; p.N = 2048; p.Ktot = 1024; p.lda = 7168; p.ldb = 1024;
    p.A = concat_p;  // first 1024 cols = rounded input
    p.B = Wci_p; p.bias1 = b_ci; p.bias2 = bias;
    p.addC = nph_p; p.addld = 2048;
    p.C2 = lcr_p; p.ldc2 = 2048;
    p.nkt = 32;
    launch_gemm(p, 8, 32, 1);
  }
  // 6) new_cell = tanh(lc @ W_fc^T + b_fc)
  {
    GP p{};
    p.M = 4096; p.N = 2048; p.Ktot = 2048; p.lda = 2048; p.ldb = 2048;
    p.A = lcr_p; p.B = Wfc_p; p.bias1 = b_fc;
    p.C1 = nc_p; p.ldc1 = 2048; p.act = 2;
    p.nkt = 64;
    launch_gemm(p, 8, 32, 1);
  }
}

// round 6
// speedup vs baseline: 1.8476x; 1.8476x over previous
#include <cuda_runtime.h>
#include <cuda_fp16.h>
#include <cstdint>
#include <math.h>

#define NT 256
#define STAGES 4
// fp16 tiles: CTA 128x256, BK=64 halves. Row pitch 72 halves (=36 words,144B).
#define A32 4608                 // A stage size in words (128*36)
#define B32 9216                 // B stage size in words (256*36)
#define ST32 13824               // stage words
#define SA_BYTES 18432
#define STAGE_BYTES 55296
#define SMEM_BYTES 221184        // 4 stages

// ---------------- scratch (fp16 operands, fp32 partials) ----------------------
__device__ __align__(16) __half g_concat[(size_t)4096 * 7168];
__device__ __align__(16) __half g_Wch2[(size_t)2048 * 7168];
__device__ __align__(16) __half g_Wcm2[(size_t)100 * 7168];
__device__ __align__(16) __half g_Wmo[(size_t)256 * 128];   // padded, cols>=100 zero
__device__ __align__(16) __half g_Wci[(size_t)2048 * 1024];
__device__ __align__(16) __half g_Wch[(size_t)2048 * 2048];
__device__ __align__(16) __half g_Wfc[(size_t)2048 * 2048];
__device__ __align__(16) __half g_nhr[(size_t)4096 * 2048]; // fp16 new_hidden
__device__ __align__(16) __half g_lcr[(size_t)4096 * 2048]; // fp16 lc
__device__ __align__(16) float  g_midp[(size_t)4 * 4096 * 256];
__device__ __align__(16) __half g_midr[(size_t)4096 * 128];

// ---------------- helpers ----------------------------------------------------
__device__ __forceinline__ void cpasync16(uint32_t saddr, const void* g, int sz) {
  asm volatile("cp.async.cg.shared.global [%0], [%1], 16, %2;\n"
               :: "r"(saddr), "l"(g), "r"(sz));
}
#define CP_COMMIT() asm volatile("cp.async.commit_group;\n" ::: "memory")

// ---------------- preprocessing ----------------------------------------------
__device__ __forceinline__ void cvt_arr(__half* __restrict__ dst,
                                        const float* __restrict__ src, int n8) {
  int stride = gridDim.x * blockDim.x;
  int i0 = blockIdx.x * blockDim.x + threadIdx.x;
  for (int i = i0; i < n8; i += 2 * stride) {
#pragma unroll
    for (int j = 0; j < 2; j++) {
      int k = i + j * stride;
      if (k < n8) {
        float4 a = ((const float4*)src)[2 * k];
        float4 b = ((const float4*)src)[2 * k + 1];
        __half2 h0 = __floats2half2_rn(a.x, a.y);
        __half2 h1 = __floats2half2_rn(a.z, a.w);
        __half2 h2 = __floats2half2_rn(b.x, b.y);
        __half2 h3 = __floats2half2_rn(b.z, b.w);
        uint4 o;
        o.x = *(const uint32_t*)&h0; o.y = *(const uint32_t*)&h1;
        o.z = *(const uint32_t*)&h2; o.w = *(const uint32_t*)&h3;
        ((uint4*)dst)[k] = o;
      }
    }
  }
}

__global__ void prep_weights(const float* W_ch2, const float* W_cm2,
                             const float* W_mo, const float* W_ci,
                             const float* W_ch, const float* W_fc) {
  cvt_arr(g_Wch2, W_ch2, (2048 * 7168) / 8);
  cvt_arr(g_Wcm2, W_cm2, (100 * 7168) / 8);
  cvt_arr(g_Wci, W_ci, (2048 * 1024) / 8);
  cvt_arr(g_Wch, W_ch, (2048 * 2048) / 8);
  cvt_arr(g_Wfc, W_fc, (2048 * 2048) / 8);
  // Wmo: 256x100 -> padded 256x128
  int stride = gridDim.x * blockDim.x;
  for (int i = blockIdx.x * blockDim.x + threadIdx.x; i < 256 * 128; i += stride) {
    int r = i >> 7, c = i & 127;
    g_Wmo[i] = (c < 100) ? __float2half_rn(W_mo[r * 100 + c]) : __half(0.f);
  }
}

__global__ void prep_concat(const float* input, const float* hidden,
                            const float* prevh, const float* cell) {
  const int n8 = 4096 * 896;  // 7168/8 units per row
  int stride = gridDim.x * blockDim.x;
  int i0 = blockIdx.x * blockDim.x + threadIdx.x;
  for (int i = i0; i < n8; i += 2 * stride) {
#pragma unroll
    for (int j = 0; j < 2; j++) {
      int k = i + j * stride;
      if (k < n8) {
        int r = k / 896;
        int c = (k - r * 896) << 3;
        const float* s;
        if (c < 1024)      s = input + (size_t)r * 1024 + c;
        else if (c < 3072) s = hidden + (size_t)r * 2048 + (c - 1024);
        else if (c < 5120) s = prevh + (size_t)r * 2048 + (c - 3072);
        else               s = cell + (size_t)r * 2048 + (c - 5120);
        float4 a = ((const float4*)s)[0];
        float4 b = ((const float4*)s)[1];
        __half2 h0 = __floats2half2_rn(a.x, a.y);
        __half2 h1 = __floats2half2_rn(a.z, a.w);
        __half2 h2 = __floats2half2_rn(b.x, b.y);
        __half2 h3 = __floats2half2_rn(b.z, b.w);
        uint4 o;
        o.x = *(const uint32_t*)&h0; o.y = *(const uint32_t*)&h1;
        o.z = *(const uint32_t*)&h2; o.w = *(const uint32_t*)&h3;
        ((uint4*)g_concat)[k] = o;
      }
    }
  }
}

// sum 4 split-K partials + bias, relu -> fp16 g_midr [4096,128]
__global__ void reduce_mid(const float* __restrict__ part,
                           const float* __restrict__ bias,
                           __half* __restrict__ outr) {
  int i = blockIdx.x * blockDim.x + threadIdx.x;
  if (i >= 4096 * 128) return;
  int r = i >> 7, c = i & 127;
  float v = 0.f;
  if (c < 100) {
    float s = bias[c];
#pragma unroll
    for (int z = 0; z < 4; z++)
      s += part[(size_t)z * 4096 * 256 + (size_t)r * 256 + c];
    v = fmaxf(s, 0.f);
  }
  outr[(size_t)r * 128 + c] = __float2half_rn(v);
}

// ---------------- main GEMM (fp16 m16n8k16) ----------------------------------
struct GP {
  int N, Ktot;             // Ktot in halves
  int lda, ldb;            // in halves
  const __half* A;
  const __half* B;
  const float* bias1;
  const float* bias2;
  const float* addC; int addld;
  float* C1; int ldc1;
  __half* C2; int ldc2;
  int act;                 // 0 none, 2 tanh
  int nkt;                 // k64-tiles per z-slice
  int partial;             // 1: raw fp32 partials at C1 + z*partStride, ld 256
  long long partStride;
};

__global__ __launch_bounds__(NT, 1)
void gemm_k(GP p) {
  extern __shared__ uint32_t sm[];
  uint32_t sbase = (uint32_t)__cvta_generic_to_shared(sm);

  const int tid  = threadIdx.x;
  const int lane = tid & 31;
  const int warp = tid >> 5;
  const int wm   = warp >> 2;    // 0..1 -> 64-row slice of 128
  const int wn   = warp & 3;     // 0..3 -> 64-col slice of 256
  const int gid  = lane >> 2;
  const int tig  = lane & 3;

  const int m0 = blockIdx.y * 128;
  const int n0 = blockIdx.x * 256;
  const int z  = blockIdx.z;
  const int kt0 = z * p.nkt;

  float acc[4][8][4];
#pragma unroll
  for (int a = 0; a < 4; a++)
#pragma unroll
    for (int b = 0; b < 8; b++)
#pragma unroll
      for (int c = 0; c < 4; c++) acc[a][b][c] = 0.f;

  auto issue = [&](int kti) {
    int buf = kti & (STAGES - 1);
    int k0 = (kt0 + kti) * 64;           // halves
    uint32_t da = sbase + buf * STAGE_BYTES;
    uint32_t db = da + SA_BYTES;
#pragma unroll
    for (int i = 0; i < 4; i++) {
      int idx = tid + i * NT;
      int row = idx >> 3;
      int c8  = (idx & 7) << 3;          // halves within row
      const __half* g = p.A + (size_t)(m0 + row) * p.lda + k0 + c8;
      int sz = (k0 + c8 < p.Ktot) ? 16 : 0;
      cpasync16(da + (uint32_t)(row * 144 + c8 * 2), g, sz);
    }
#pragma unroll
    for (int i = 0; i < 8; i++) {
      int idx = tid + i * NT;
      int row = idx >> 3;
      int c8  = (idx & 7) << 3;
      const __half* g = p.B + (size_t)(n0 + row) * p.ldb + k0 + c8;
      int sz = ((k0 + c8 < p.Ktot) && (n0 + row < p.N)) ? 16 : 0;
      cpasync16(db + (uint32_t)(row * 144 + c8 * 2), g, sz);
    }
  };

  uint32_t af[2][4][4], bf[2][8][2];

  const int nkt = p.nkt;
#pragma unroll
  for (int s = 0; s < STAGES - 1; s++) {
    if (s < nkt) issue(s);
    CP_COMMIT();
  }

  for (int kt = 0; kt < nkt; kt++) {
    asm volatile("cp.async.wait_group %0;\n" :: "n"(STAGES - 2) : "memory");
    __syncthreads();
    int buf = kt & (STAGES - 1);
    const uint32_t* a = sm + buf * ST32;
    const uint32_t* b = a + A32;

    auto lfrag = [&](int ks, int sl) {
      const int c = ks * 8 + tig;
#pragma unroll
      for (int tm = 0; tm < 4; tm++) {
        int r = wm * 64 + tm * 16 + gid;
        af[sl][tm][0] = a[r * 36 + c];
        af[sl][tm][1] = a[(r + 8) * 36 + c];
        af[sl][tm][2] = a[r * 36 + c + 4];
        af[sl][tm][3] = a[(r + 8) * 36 + c + 4];
      }
#pragma unroll
      for (int tn = 0; tn < 8; tn++) {
        int n = wn * 64 + tn * 8 + gid;
        bf[sl][tn][0] = b[n * 36 + c];
        bf[sl][tn][1] = b[n * 36 + c + 4];
      }
    };
    auto domma = [&](int sl) {
#pragma unroll
      for (int tm = 0; tm < 4; tm++)
#pragma unroll
        for (int tn = 0; tn < 8; tn++) {
          asm volatile(
              "mma.sync.aligned.m16n8k16.row.col.f32.f16.f16.f32 "
              "{%0,%1,%2,%3}, {%4,%5,%6,%7}, {%8,%9}, {%0,%1,%2,%3};\n"
              : "+f"(acc[tm][tn][0]), "+f"(acc[tm][tn][1]),
                "+f"(acc[tm][tn][2]), "+f"(acc[tm][tn][3])
              : "r"(af[sl][tm][0]), "r"(af[sl][tm][1]),
                "r"(af[sl][tm][2]), "r"(af[sl][tm][3]),
                "r"(bf[sl][tn][0]), "r"(bf[sl][tn][1]));
        }
    };

    lfrag(0, 0);                      // first fragment of this tile
    if (kt + STAGES - 1 < nkt) issue(kt + STAGES - 1);
    CP_COMMIT();
#pragma unroll
    for (int ks = 0; ks < 4; ks++) {  // 4 x k16 per k64 tile
      if (ks < 3) lfrag(ks + 1, (ks + 1) & 1);
      domma(ks & 1);
    }
  }

  // ---- epilogue ----
  if (p.partial) {
    float* cbase = p.C1 + (size_t)z * p.partStride;
#pragma unroll
    for (int tm = 0; tm < 4; tm++) {
      int r0 = m0 + wm * 64 + tm * 16 + gid;
#pragma unroll
      for (int tn = 0; tn < 8; tn++) {
        int c0 = n0 + wn * 64 + tn * 8 + 2 * tig;
#pragma unroll
        for (int h = 0; h < 2; h++) {
          float2 v = make_float2(acc[tm][tn][h * 2], acc[tm][tn][h * 2 + 1]);
          *(float2*)(cbase + (size_t)(r0 + h * 8) * 256 + c0) = v;
        }
      }
    }
    return;
  }

#pragma unroll
  for (int tn = 0; tn < 8; tn++) {
    int c0 = n0 + wn * 64 + tn * 8 + 2 * tig;
    if (c0 >= p.N) continue;
    float b0 = p.bias1[c0], b1 = p.bias1[c0 + 1];
    if (p.bias2) { b0 += p.bias2[c0]; b1 += p.bias2[c0 + 1]; }
#pragma unroll
    for (int tm = 0; tm < 4; tm++) {
      int r0 = m0 + wm * 64 + tm * 16 + gid;
#pragma unroll
      for (int h = 0; h < 2; h++) {
        int r = r0 + h * 8;
        float vx = acc[tm][tn][h * 2] + b0;
        float vy = acc[tm][tn][h * 2 + 1] + b1;
        if (p.addC) {
          float2 ad = *(const float2*)(p.addC + (size_t)r * p.addld + c0);
          vx += ad.x; vy += ad.y;
        }
        if (p.act == 2) { vx = tanhf(vx); vy = tanhf(vy); }
        if (p.C1)
          *(float2*)(p.C1 + (size_t)r * p.ldc1 + c0) = make_float2(vx, vy);
        if (p.C2) {
          __half2 hh = __floats2half2_rn(vx, vy);
          *(__half2*)(p.C2 + (size_t)r * p.ldc2 + c0) = hh;
        }
      }
    }
  }
}

// ---------------- host --------------------------------------------------------
static void launch_gemm(const GP& p, int gx, int gy, int gz) {
  gemm_k<<<dim3(gx, gy, gz), NT, SMEM_BYTES>>>(p);
}

extern "C" void kernel_launch(void* const* d_in, const int* in_sizes, int n_in,
                              void* d_out, int out_size) {
  (void)in_sizes; (void)n_in; (void)out_size;
  const float* input  = (const float*)d_in[0];
  const float* hidden = (const float*)d_in[1];
  const float* prevh  = (const float*)d_in[2];
  const float* cell   = (const float*)d_in[3];
  const float* W_ch2  = (const float*)d_in[4];
  const float* b_ch2  = (const float*)d_in[5];
  const float* W_cm2  = (const float*)d_in[6];
  const float* b_cm2  = (const float*)d_in[7];
  const float* W_mo   = (const float*)d_in[8];
  const float* b_mo   = (const float*)d_in[9];
  const float* W_ci   = (const float*)d_in[10];
  const float* b_ci   = (const float*)d_in[11];
  const float* W_ch   = (const float*)d_in[12];
  const float* b_ch   = (const float*)d_in[13];
  const float* W_fc   = (const float*)d_in[14];
  const float* b_fc   = (const float*)d_in[15];
  const float* bias   = (const float*)d_in[16];

  float* out_p = (float*)d_out;                 // [4096,256]
  float* nh_p  = out_p + (size_t)4096 * 256;    // new_hidden
  float* nc_p  = nh_p + (size_t)4096 * 2048;    // new_cell
  float* nph_p = nc_p + (size_t)4096 * 2048;    // new_prev_hidden (= h_proj)

  __half *concat_p, *Wch2_p, *Wcm2_p, *Wmo_p, *Wci_p, *Wch_p, *Wfc_p;
  __half *nhr_p, *lcr_p, *midr_p;
  float* midp_p;
  cudaGetSymbolAddress((void**)&concat_p, g_concat);
  cudaGetSymbolAddress((void**)&Wch2_p, g_Wch2);
  cudaGetSymbolAddress((void**)&Wcm2_p, g_Wcm2);
  cudaGetSymbolAddress((void**)&Wmo_p, g_Wmo);
  cudaGetSymbolAddress((void**)&Wci_p, g_Wci);
  cudaGetSymbolAddress((void**)&Wch_p, g_Wch);
  cudaGetSymbolAddress((void**)&Wfc_p, g_Wfc);
  cudaGetSymbolAddress((void**)&nhr_p, g_nhr);
  cudaGetSymbolAddress((void**)&lcr_p, g_lcr);
  cudaGetSymbolAddress((void**)&midp_p, g_midp);
  cudaGetSymbolAddress((void**)&midr_p, g_midr);

  cudaFuncSetAttribute(gemm_k, cudaFuncAttributeMaxDynamicSharedMemorySize,
                       SMEM_BYTES);

  // L0, L1: preprocessing (fp32 -> fp16)
  prep_weights<<<2048, 256>>>(W_ch2, W_cm2, W_mo, W_ci, W_ch, W_fc);
  prep_concat<<<2048, 256>>>(input, hidden, prevh, cell);

  // L2: G1  new_hidden = concat @ W_ch2^T + b_ch2  (fp32->nh, fp16->nhr)
  {
    GP p{};
    p.N = 2048; p.Ktot = 7168; p.lda = 7168; p.ldb = 7168;
    p.A = concat_p; p.B = Wch2_p; p.bias1 = b_ch2;
    p.C1 = nh_p; p.ldc1 = 2048; p.C2 = nhr_p; p.ldc2 = 2048;
    p.nkt = 112;
    launch_gemm(p, 8, 32, 1);
  }
  // L3: G2  mid partials = concat @ W_cm2^T  (split-K x4)
  {
    GP p{};
    p.N = 100; p.Ktot = 7168; p.lda = 7168; p.ldb = 7168;
    p.A = concat_p; p.B = Wcm2_p;
    p.C1 = midp_p; p.partial = 1; p.partStride = (long long)4096 * 256;
    p.nkt = 28;  // 28*64*4 = 7168
    launch_gemm(p, 1, 32, 4);
  }
  // L4: reduce -> fp16 mid
  reduce_mid<<<(4096 * 128 + 255) / 256, 256>>>(midp_p, b_cm2, midr_p);
  // L5: G4  h_proj = new_hidden @ W_ch^T + b_ch -> new_prev_hidden  (ncu target)
  {
    GP p{};
    p.N = 2048; p.Ktot = 2048; p.lda = 2048; p.ldb = 2048;
    p.A = nhr_p; p.B = Wch_p; p.bias1 = b_ch;
    p.C1 = nph_p; p.ldc1 = 2048;
    p.nkt = 32;
    launch_gemm(p, 8, 32, 1);
  }
  // L6: G3  out = mid @ W_mo^T + b_mo  (K padded to 128)
  {
    GP p{};
    p.N = 256; p.Ktot = 128; p.lda = 128; p.ldb = 128;
    p.A = midr_p; p.B = Wmo_p; p.bias1 = b_mo;
    p.C1 = out_p; p.ldc1 = 256;
    p.nkt = 2;
    launch_gemm(p, 1, 32, 1);
  }
  // L7: G5  lc = input @ W_ci^T + b_ci + bias + h_proj  (fp16->lcr)
  {
    GP p{};
    p.N = 2048; p.Ktot = 1024; p.lda = 7168; p.ldb = 1024;
    p.A = concat_p;  // first 1024 halves of each row = fp16 input
    p.B = Wci_p; p.bias1 = b_ci; p.bias2 = bias;
    p.addC = nph_p; p.addld = 2048;
    p.C2 = lcr_p; p.ldc2 = 2048;
    p.nkt = 16;
    launch_gemm(p, 8, 32, 1);
  }
  // L8: G6  new_cell = tanh(lc @ W_fc^T + b_fc)
  {
    GP p{};
    p.N = 2048; p.Ktot = 2048; p.lda = 2048; p.ldb = 2048;
    p.A = lcr_p; p.B = Wfc_p; p.bias1 = b_fc;
    p.C1 = nc_p; p.ldc1 = 2048; p.act = 2;
    p.nkt = 32;
    launch_gemm(p, 8, 32, 1);
  }
}

// round 7
// speedup vs baseline: 2.0552x; 1.1124x over previous
#include <cuda_runtime.h>
#include <cuda_fp16.h>
#include <cstdint>
#include <math.h>

#define NT 256
#define STAGES 4
// fp16: CTA 128x256, BK=64 halves. Row pitch 72 halves = 36 words = 144B.
#define A32 4608
#define B32 9216
#define ST32 13824
#define SA_BYTES 18432
#define STAGE_BYTES 55296
#define SMEM_BYTES 221184

// ---------------- scratch -----------------------------------------------------
__device__ __align__(16) __half g_concat[(size_t)4096 * 7168];
__device__ __align__(16) __half g_Wcomb[(size_t)2304 * 7168]; // [Wch2;Wcm2;pad]
__device__ __align__(16) __half g_Wmo[(size_t)256 * 128];     // padded, >=100 zero
__device__ __align__(16) __half g_Wci[(size_t)2048 * 1024];
__device__ __align__(16) __half g_Wch[(size_t)2048 * 2048];
__device__ __align__(16) __half g_Wfc[(size_t)2048 * 2048];
__device__ __align__(16) __half g_nhr[(size_t)4096 * 2048];   // fp16 new_hidden
__device__ __align__(16) __half g_lcr[(size_t)4096 * 2048];   // fp16 lc
__device__ __align__(16) __half g_midr[(size_t)4096 * 128];   // fp16 relu(mid)

// ---------------- helpers -----------------------------------------------------
__device__ __forceinline__ void cpasync16(uint32_t saddr, const void* g, int sz) {
  asm volatile("cp.async.cg.shared.global [%0], [%1], 16, %2;\n"
               :: "r"(saddr), "l"(g), "r"(sz));
}
#define CP_COMMIT() asm volatile("cp.async.commit_group;\n" ::: "memory")
#define LDSM_X4(r0, r1, r2, r3, addr) \
  asm volatile("ldmatrix.sync.aligned.m8n8.x4.shared.b16 {%0,%1,%2,%3}, [%4];" \
               : "=r"(r0), "=r"(r1), "=r"(r2), "=r"(r3) : "r"(addr))

// ---------------- preprocessing -----------------------------------------------
__device__ __forceinline__ void cvt_arr(__half* __restrict__ dst,
                                        const float* __restrict__ src, int n8) {
  int stride = gridDim.x * blockDim.x;
  int i0 = blockIdx.x * blockDim.x + threadIdx.x;
  for (int i = i0; i < n8; i += 4 * stride) {
#pragma unroll
    for (int j = 0; j < 4; j++) {
      int k = i + j * stride;
      if (k < n8) {
        float4 a = ((const float4*)src)[2 * k];
        float4 b = ((const float4*)src)[2 * k + 1];
        __half2 h0 = __floats2half2_rn(a.x, a.y);
        __half2 h1 = __floats2half2_rn(a.z, a.w);
        __half2 h2 = __floats2half2_rn(b.x, b.y);
        __half2 h3 = __floats2half2_rn(b.z, b.w);
        uint4 o;
        o.x = *(const uint32_t*)&h0; o.y = *(const uint32_t*)&h1;
        o.z = *(const uint32_t*)&h2; o.w = *(const uint32_t*)&h3;
        ((uint4*)dst)[k] = o;
      }
    }
  }
}

__global__ void prep_weights(const float* W_ch2, const float* W_cm2,
                             const float* W_mo, const float* W_ci,
                             const float* W_ch, const float* W_fc) {
  cvt_arr(g_Wcomb, W_ch2, (2048 * 7168) / 8);
  cvt_arr(g_Wcomb + (size_t)2048 * 7168, W_cm2, (100 * 7168) / 8);
  cvt_arr(g_Wci, W_ci, (2048 * 1024) / 8);
  cvt_arr(g_Wch, W_ch, (2048 * 2048) / 8);
  cvt_arr(g_Wfc, W_fc, (2048 * 2048) / 8);
  int stride = gridDim.x * blockDim.x;
  for (int i = blockIdx.x * blockDim.x + threadIdx.x; i < 256 * 128; i += stride) {
    int r = i >> 7, c = i & 127;
    g_Wmo[i] = (c < 100) ? __float2half_rn(W_mo[r * 100 + c]) : __half(0.f);
  }
}

__global__ void prep_concat(const float* input, const float* hidden,
                            const float* prevh, const float* cell) {
  const int n8 = 4096 * 896;
  int stride = gridDim.x * blockDim.x;
  int i0 = blockIdx.x * blockDim.x + threadIdx.x;
  for (int i = i0; i < n8; i += 4 * stride) {
#pragma unroll
    for (int j = 0; j < 4; j++) {
      int k = i + j * stride;
      if (k < n8) {
        int r = k / 896;
        int c = (k - r * 896) << 3;
        const float* s;
        if (c < 1024)      s = input + (size_t)r * 1024 + c;
        else if (c < 3072) s = hidden + (size_t)r * 2048 + (c - 1024);
        else if (c < 5120) s = prevh + (size_t)r * 2048 + (c - 3072);
        else               s = cell + (size_t)r * 2048 + (c - 5120);
        float4 a = ((const float4*)s)[0];
        float4 b = ((const float4*)s)[1];
        __half2 h0 = __floats2half2_rn(a.x, a.y);
        __half2 h1 = __floats2half2_rn(a.z, a.w);
        __half2 h2 = __floats2half2_rn(b.x, b.y);
        __half2 h3 = __floats2half2_rn(b.z, b.w);
        uint4 o;
        o.x = *(const uint32_t*)&h0; o.y = *(const uint32_t*)&h1;
        o.z = *(const uint32_t*)&h2; o.w = *(const uint32_t*)&h3;
        ((uint4*)g_concat)[k] = o;
      }
    }
  }
}

// ---------------- main GEMM (fp16 m16n8k16, ldmatrix) -------------------------
struct GP {
  int N, Ktot;             // in halves
  int lda, ldb;            // in halves
  const __half* A;
  const __half* B;
  const float* bias1;
  const float* bias2;
  const float* addC; int addld;
  float* C1; int ldc1;
  __half* C2; int ldc2;
  __half* midC;            // fused-mid output (cols >= 2048), pitch 128
  const float* midBias;
  int act;                 // 0 none, 2 tanh
  int nkt;
};

__global__ __launch_bounds__(NT, 1)
void gemm_k(GP p) {
  extern __shared__ uint32_t sm[];
  uint32_t sbase = (uint32_t)__cvta_generic_to_shared(sm);

  const int tid  = threadIdx.x;
  const int lane = tid & 31;
  const int warp = tid >> 5;
  const int wm   = warp >> 2;    // 0..1 -> 64-row slice of 128
  const int wn   = warp & 3;     // 0..3 -> 64-col slice of 256
  const int gid  = lane >> 2;
  const int tig  = lane & 3;

  const int m0 = blockIdx.y * 128;
  const int n0 = blockIdx.x * 256;

  // ldmatrix per-lane base offsets (bytes within stage)
  const uint32_t aB = (uint32_t)(((wm * 64 + (lane & 15)) * 36 +
                                  ((lane >> 4) << 2)) << 2);
  const uint32_t bB = (uint32_t)(((wn * 64 + (lane & 7) + ((lane >> 4) << 3)) * 36 +
                                  (((lane >> 3) & 1) << 2)) << 2);

  float acc[4][8][4];
#pragma unroll
  for (int a = 0; a < 4; a++)
#pragma unroll
    for (int b = 0; b < 8; b++)
#pragma unroll
      for (int c = 0; c < 4; c++) acc[a][b][c] = 0.f;

  auto issue = [&](int kti) {
    int buf = kti & (STAGES - 1);
    int k0 = kti * 64;
    uint32_t da = sbase + buf * STAGE_BYTES;
    uint32_t db = da + SA_BYTES;
#pragma unroll
    for (int i = 0; i < 4; i++) {
      int idx = tid + i * NT;
      int row = idx >> 3;
      int c8  = (idx & 7) << 3;
      const __half* g = p.A + (size_t)(m0 + row) * p.lda + k0 + c8;
      int sz = (k0 + c8 < p.Ktot) ? 16 : 0;
      cpasync16(da + (uint32_t)(row * 144 + c8 * 2), g, sz);
    }
#pragma unroll
    for (int i = 0; i < 8; i++) {
      int idx = tid + i * NT;
      int row = idx >> 3;
      int c8  = (idx & 7) << 3;
      const __half* g = p.B + (size_t)(n0 + row) * p.ldb + k0 + c8;
      int sz = ((k0 + c8 < p.Ktot) && (n0 + row < p.N)) ? 16 : 0;
      cpasync16(db + (uint32_t)(row * 144 + c8 * 2), g, sz);
    }
  };

  uint32_t af[2][4][4], bf[2][8][2];

  const int nkt = p.nkt;
#pragma unroll
  for (int s = 0; s < STAGES - 1; s++) {
    if (s < nkt) issue(s);
    CP_COMMIT();
  }

  for (int kt = 0; kt < nkt; kt++) {
    asm volatile("cp.async.wait_group %0;\n" :: "n"(STAGES - 2) : "memory");
    __syncthreads();
    int buf = kt & (STAGES - 1);
    uint32_t sst = sbase + buf * STAGE_BYTES;

    auto lfrag = [&](int ks, int sl) {
      uint32_t ka = sst + aB + (uint32_t)(ks * 32);
#pragma unroll
      for (int tm = 0; tm < 4; tm++) {
        LDSM_X4(af[sl][tm][0], af[sl][tm][1], af[sl][tm][2], af[sl][tm][3],
                ka + tm * 2304u);
      }
      uint32_t kb = sst + SA_BYTES + bB + (uint32_t)(ks * 32);
#pragma unroll
      for (int pr = 0; pr < 4; pr++) {
        LDSM_X4(bf[sl][2 * pr][0], bf[sl][2 * pr][1],
                bf[sl][2 * pr + 1][0], bf[sl][2 * pr + 1][1],
                kb + pr * 2304u);
      }
    };
    auto domma = [&](int sl) {
#pragma unroll
      for (int tm = 0; tm < 4; tm++)
#pragma unroll
        for (int tn = 0; tn < 8; tn++) {
          asm volatile(
              "mma.sync.aligned.m16n8k16.row.col.f32.f16.f16.f32 "
              "{%0,%1,%2,%3}, {%4,%5,%6,%7}, {%8,%9}, {%0,%1,%2,%3};\n"
              : "+f"(acc[tm][tn][0]), "+f"(acc[tm][tn][1]),
                "+f"(acc[tm][tn][2]), "+f"(acc[tm][tn][3])
              : "r"(af[sl][tm][0]), "r"(af[sl][tm][1]),
                "r"(af[sl][tm][2]), "r"(af[sl][tm][3]),
                "r"(bf[sl][tn][0]), "r"(bf[sl][tn][1]));
        }
    };

    lfrag(0, 0);
    if (kt + STAGES - 1 < nkt) issue(kt + STAGES - 1);
    CP_COMMIT();
#pragma unroll
    for (int ks = 0; ks < 4; ks++) {
      if (ks < 3) lfrag(ks + 1, (ks + 1) & 1);
      domma(ks & 1);
    }
  }

  // ---- epilogue ----
#pragma unroll
  for (int tn = 0; tn < 8; tn++) {
    int c0 = n0 + wn * 64 + tn * 8 + 2 * tig;
    if (p.midC && c0 >= 2048) {
      // fused mid columns: relu -> fp16, pitch 128
      int cm = c0 - 2048;
      if (cm < 100) {
        float b0 = p.midBias[cm], b1 = p.midBias[cm + 1];
#pragma unroll
        for (int tm = 0; tm < 4; tm++) {
          int r0 = m0 + wm * 64 + tm * 16 + gid;
#pragma unroll
          for (int h = 0; h < 2; h++) {
            int r = r0 + h * 8;
            float vx = fmaxf(acc[tm][tn][h * 2] + b0, 0.f);
            float vy = fmaxf(acc[tm][tn][h * 2 + 1] + b1, 0.f);
            *(__half2*)(p.midC + (size_t)r * 128 + cm) = __floats2half2_rn(vx, vy);
          }
        }
      }
      continue;
    }
    if (c0 >= p.N) continue;
    float b0 = p.bias1[c0], b1 = p.bias1[c0 + 1];
    if (p.bias2) { b0 += p.bias2[c0]; b1 += p.bias2[c0 + 1]; }
#pragma unroll
    for (int tm = 0; tm < 4; tm++) {
      int r0 = m0 + wm * 64 + tm * 16 + gid;
#pragma unroll
      for (int h = 0; h < 2; h++) {
        int r = r0 + h * 8;
        float vx = acc[tm][tn][h * 2] + b0;
        float vy = acc[tm][tn][h * 2 + 1] + b1;
        if (p.addC) {
          float2 ad = *(const float2*)(p.addC + (size_t)r * p.addld + c0);
          vx += ad.x; vy += ad.y;
        }
        if (p.act == 2) { vx = tanhf(vx); vy = tanhf(vy); }
        if (p.C1)
          *(float2*)(p.C1 + (size_t)r * p.ldc1 + c0) = make_float2(vx, vy);
        if (p.C2)
          *(__half2*)(p.C2 + (size_t)r * p.ldc2 + c0) = __floats2half2_rn(vx, vy);
      }
    }
  }
}

// ---------------- host --------------------------------------------------------
static void launch_gemm(const GP& p, int gx, int gy) {
  gemm_k<<<dim3(gx, gy, 1), NT, SMEM_BYTES>>>(p);
}

extern "C" void kernel_launch(void* const* d_in, const int* in_sizes, int n_in,
                              void* d_out, int out_size) {
  (void)in_sizes; (void)n_in; (void)out_size;
  const float* input  = (const float*)d_in[0];
  const float* hidden = (const float*)d_in[1];
  const float* prevh  = (const float*)d_in[2];
  const float* cell   = (const float*)d_in[3];
  const float* W_ch2  = (const float*)d_in[4];
  const float* b_ch2  = (const float*)d_in[5];
  const float* W_cm2  = (const float*)d_in[6];
  const float* b_cm2  = (const float*)d_in[7];
  const float* W_mo   = (const float*)d_in[8];
  const float* b_mo   = (const float*)d_in[9];
  const float* W_ci   = (const float*)d_in[10];
  const float* b_ci   = (const float*)d_in[11];
  const float* W_ch   = (const float*)d_in[12];
  const float* b_ch   = (const float*)d_in[13];
  const float* W_fc   = (const float*)d_in[14];
  const float* b_fc   = (const float*)d_in[15];
  const float* bias   = (const float*)d_in[16];

  float* out_p = (float*)d_out;                 // [4096,256]
  float* nh_p  = out_p + (size_t)4096 * 256;    // new_hidden
  float* nc_p  = nh_p + (size_t)4096 * 2048;    // new_cell
  float* nph_p = nc_p + (size_t)4096 * 2048;    // new_prev_hidden (= h_proj)

  __half *concat_p, *Wcomb_p, *Wmo_p, *Wci_p, *Wch_p, *Wfc_p;
  __half *nhr_p, *lcr_p, *midr_p;
  cudaGetSymbolAddress((void**)&concat_p, g_concat);
  cudaGetSymbolAddress((void**)&Wcomb_p, g_Wcomb);
  cudaGetSymbolAddress((void**)&Wmo_p, g_Wmo);
  cudaGetSymbolAddress((void**)&Wci_p, g_Wci);
  cudaGetSymbolAddress((void**)&Wch_p, g_Wch);
  cudaGetSymbolAddress((void**)&Wfc_p, g_Wfc);
  cudaGetSymbolAddress((void**)&nhr_p, g_nhr);
  cudaGetSymbolAddress((void**)&lcr_p, g_lcr);
  cudaGetSymbolAddress((void**)&midr_p, g_midr);

  cudaFuncSetAttribute(gemm_k, cudaFuncAttributeMaxDynamicSharedMemorySize,
                       SMEM_BYTES);

  // L0, L1: preprocessing (fp32 -> fp16)
  prep_weights<<<2048, 256>>>(W_ch2, W_cm2, W_mo, W_ci, W_ch, W_fc);
  prep_concat<<<2048, 256>>>(input, hidden, prevh, cell);

  // L2: G1+G2 fused: [new_hidden | mid] = concat @ [Wch2;Wcm2]^T
  {
    GP p{};
    p.N = 2148; p.Ktot = 7168; p.lda = 7168; p.ldb = 7168;
    p.A = concat_p; p.B = Wcomb_p; p.bias1 = b_ch2;
    p.C1 = nh_p; p.ldc1 = 2048; p.C2 = nhr_p; p.ldc2 = 2048;
    p.midC = midr_p; p.midBias = b_cm2;
    p.nkt = 112;
    launch_gemm(p, 9, 32);
  }
  // L3: G4  h_proj = new_hidden @ W_ch^T + b_ch -> new_prev_hidden
  {
    GP p{};
    p.N = 2048; p.Ktot = 2048; p.lda = 2048; p.ldb = 2048;
    p.A = nhr_p; p.B = Wch_p; p.bias1 = b_ch;
    p.C1 = nph_p; p.ldc1 = 2048;
    p.nkt = 32;
    launch_gemm(p, 8, 32);
  }
  // L4: G5  lc = input @ W_ci^T + b_ci + bias + h_proj  (fp16->lcr)
  {
    GP p{};
    p.N = 2048; p.Ktot = 1024; p.lda = 7168; p.ldb = 1024;
    p.A = concat_p;  // first 1024 halves per row = fp16 input
    p.B = Wci_p; p.bias1 = b_ci; p.bias2 = bias;
    p.addC = nph_p; p.addld = 2048;
    p.C2 = lcr_p; p.ldc2 = 2048;
    p.nkt = 16;
    launch_gemm(p, 8, 32);
  }
  // L5: G6  new_cell = tanh(lc @ W_fc^T + b_fc)   <- ncu capture target
  {
    GP p{};
    p.N = 2048; p.Ktot = 2048; p.lda = 2048; p.ldb = 2048;
    p.A = lcr_p; p.B = Wfc_p; p.bias1 = b_fc;
    p.C1 = nc_p; p.ldc1 = 2048; p.act = 2;
    p.nkt = 32;
    launch_gemm(p, 8, 32);
  }
  // L6: G3  out = mid @ W_mo^T + b_mo  (K padded to 128)
  {
    GP p{};
    p.N = 256; p.Ktot = 128; p.lda = 128; p.ldb = 128;
    p.A = midr_p; p.B = Wmo_p; p.bias1 = b_mo;
    p.C1 = out_p; p.ldc1 = 256;
    p.nkt = 2;
    launch_gemm(p, 1, 32);
  }
}

// round 8
// speedup vs baseline: 2.2501x; 1.0949x over previous
#include <cuda_runtime.h>
#include <cuda_fp16.h>
#include <cstdint>
#include <math.h>

#define NT 128
#define STAGES 3
// fp16: CTA 128x128, BK=64 halves. Row pitch 72 halves = 36 words = 144B.
#define SA_BYTES 18432           // 128 rows x 144B
#define STAGE_BYTES 36864        // A + B
#define SMEM_BYTES 110592        // 3 stages -> 2 CTAs/SM

// ---------------- scratch -----------------------------------------------------
__device__ __align__(16) __half g_concat[(size_t)4096 * 7168];
__device__ __align__(16) __half g_Wcomb[(size_t)2304 * 7168]; // [Wch2;Wcm2;pad]
__device__ __align__(16) __half g_Wmo[(size_t)256 * 128];     // padded, >=100 zero
__device__ __align__(16) __half g_Wci[(size_t)2048 * 1024];
__device__ __align__(16) __half g_Wch[(size_t)2048 * 2048];
__device__ __align__(16) __half g_Wfc[(size_t)2048 * 2048];
__device__ __align__(16) __half g_nhr[(size_t)4096 * 2048];   // fp16 new_hidden
__device__ __align__(16) __half g_lcr[(size_t)4096 * 2048];   // fp16 lc
__device__ __align__(16) __half g_midr[(size_t)4096 * 128];   // fp16 relu(mid)

// ---------------- helpers -----------------------------------------------------
__device__ __forceinline__ void cpasync16(uint32_t saddr, const void* g, int sz) {
  asm volatile("cp.async.cg.shared.global [%0], [%1], 16, %2;\n"
               :: "r"(saddr), "l"(g), "r"(sz));
}
#define CP_COMMIT() asm volatile("cp.async.commit_group;\n" ::: "memory")
#define LDSM_X4(r0, r1, r2, r3, addr) \
  asm volatile("ldmatrix.sync.aligned.m8n8.x4.shared.b16 {%0,%1,%2,%3}, [%4];" \
               : "=r"(r0), "=r"(r1), "=r"(r2), "=r"(r3) : "r"(addr))

// ---------------- preprocessing -----------------------------------------------
__device__ __forceinline__ void cvt_arr(__half* __restrict__ dst,
                                        const float* __restrict__ src, int n8) {
  int stride = gridDim.x * blockDim.x;
  int i0 = blockIdx.x * blockDim.x + threadIdx.x;
  for (int i = i0; i < n8; i += 4 * stride) {
#pragma unroll
    for (int j = 0; j < 4; j++) {
      int k = i + j * stride;
      if (k < n8) {
        float4 a = ((const float4*)src)[2 * k];
        float4 b = ((const float4*)src)[2 * k + 1];
        __half2 h0 = __floats2half2_rn(a.x, a.y);
        __half2 h1 = __floats2half2_rn(a.z, a.w);
        __half2 h2 = __floats2half2_rn(b.x, b.y);
        __half2 h3 = __floats2half2_rn(b.z, b.w);
        uint4 o;
        o.x = *(const uint32_t*)&h0; o.y = *(const uint32_t*)&h1;
        o.z = *(const uint32_t*)&h2; o.w = *(const uint32_t*)&h3;
        ((uint4*)dst)[k] = o;
      }
    }
  }
}

__global__ void prep_weights(const float* W_ch2, const float* W_cm2,
                             const float* W_mo, const float* W_ci,
                             const float* W_ch, const float* W_fc) {
  cvt_arr(g_Wcomb, W_ch2, (2048 * 7168) / 8);
  cvt_arr(g_Wcomb + (size_t)2048 * 7168, W_cm2, (100 * 7168) / 8);
  cvt_arr(g_Wci, W_ci, (2048 * 1024) / 8);
  cvt_arr(g_Wch, W_ch, (2048 * 2048) / 8);
  cvt_arr(g_Wfc, W_fc, (2048 * 2048) / 8);
  int stride = gridDim.x * blockDim.x;
  for (int i = blockIdx.x * blockDim.x + threadIdx.x; i < 256 * 128; i += stride) {
    int r = i >> 7, c = i & 127;
    g_Wmo[i] = (c < 100) ? __float2half_rn(W_mo[r * 100 + c]) : __half(0.f);
  }
}

__global__ void prep_concat(const float* input, const float* hidden,
                            const float* prevh, const float* cell) {
  const int n8 = 4096 * 896;
  int stride = gridDim.x * blockDim.x;
  int i0 = blockIdx.x * blockDim.x + threadIdx.x;
  for (int i = i0; i < n8; i += 4 * stride) {
#pragma unroll
    for (int j = 0; j < 4; j++) {
      int k = i + j * stride;
      if (k < n8) {
        int r = k / 896;
        int c = (k - r * 896) << 3;
        const float* s;
        if (c < 1024)      s = input + (size_t)r * 1024 + c;
        else if (c < 3072) s = hidden + (size_t)r * 2048 + (c - 1024);
        else if (c < 5120) s = prevh + (size_t)r * 2048 + (c - 3072);
        else               s = cell + (size_t)r * 2048 + (c - 5120);
        float4 a = ((const float4*)s)[0];
        float4 b = ((const float4*)s)[1];
        __half2 h0 = __floats2half2_rn(a.x, a.y);
        __half2 h1 = __floats2half2_rn(a.z, a.w);
        __half2 h2 = __floats2half2_rn(b.x, b.y);
        __half2 h3 = __floats2half2_rn(b.z, b.w);
        uint4 o;
        o.x = *(const uint32_t*)&h0; o.y = *(const uint32_t*)&h1;
        o.z = *(const uint32_t*)&h2; o.w = *(const uint32_t*)&h3;
        ((uint4*)g_concat)[k] = o;
      }
    }
  }
}

// ---------------- main GEMM (fp16 m16n8k16, ldmatrix, 128x128 CTA) ------------
struct GP {
  int N, Ktot;             // in halves
  int lda, ldb;            // in halves
  const __half* A;
  const __half* B;
  const float* bias1;
  const float* bias2;
  const float* addC; int addld;
  float* C1; int ldc1;
  __half* C2; int ldc2;
  __half* midC;            // fused-mid output (cols >= 2048), pitch 128
  const float* midBias;
  int act;                 // 0 none, 2 tanh
  int nkt;
  int gxMain;              // bx >= gxMain -> use secondary GP
};

__global__ __launch_bounds__(NT, 2)
void gemm_k(GP p, GP q) {
  extern __shared__ uint32_t sm[];
  uint32_t sbase = (uint32_t)__cvta_generic_to_shared(sm);

  const bool useQ = ((int)blockIdx.x >= p.gxMain);
  const GP P = useQ ? q : p;
  const int bx = useQ ? ((int)blockIdx.x - p.gxMain) : (int)blockIdx.x;

  const int tid  = threadIdx.x;
  const int lane = tid & 31;
  const int warp = tid >> 5;
  const int wm   = warp >> 1;    // 0..1 -> 64-row slice of 128
  const int wn   = warp & 1;     // 0..1 -> 64-col slice of 128
  const int gid  = lane >> 2;
  const int tig  = lane & 3;

  const int m0 = blockIdx.y * 128;
  const int n0 = bx * 128;

  // ldmatrix per-lane base offsets (bytes within stage)
  const uint32_t aB = (uint32_t)(((wm * 64 + (lane & 15)) * 36 +
                                  ((lane >> 4) << 2)) << 2);
  const uint32_t bB = (uint32_t)(((wn * 64 + (lane & 7) + ((lane >> 4) << 3)) * 36 +
                                  (((lane >> 3) & 1) << 2)) << 2);

  float acc[4][8][4];
#pragma unroll
  for (int a = 0; a < 4; a++)
#pragma unroll
    for (int b = 0; b < 8; b++)
#pragma unroll
      for (int c = 0; c < 4; c++) acc[a][b][c] = 0.f;

  auto issue = [&](int kti) {
    int buf = kti % STAGES;
    int k0 = kti * 64;
    uint32_t da = sbase + buf * STAGE_BYTES;
    uint32_t db = da + SA_BYTES;
#pragma unroll
    for (int i = 0; i < 8; i++) {
      int idx = tid + i * NT;
      int row = idx >> 3;
      int c8  = (idx & 7) << 3;
      const __half* g = P.A + (size_t)(m0 + row) * P.lda + k0 + c8;
      int sz = (k0 + c8 < P.Ktot) ? 16 : 0;
      cpasync16(da + (uint32_t)(row * 144 + c8 * 2), g, sz);
    }
#pragma unroll
    for (int i = 0; i < 8; i++) {
      int idx = tid + i * NT;
      int row = idx >> 3;
      int c8  = (idx & 7) << 3;
      const __half* g = P.B + (size_t)(n0 + row) * P.ldb + k0 + c8;
      int sz = ((k0 + c8 < P.Ktot) && (n0 + row < P.N)) ? 16 : 0;
      cpasync16(db + (uint32_t)(row * 144 + c8 * 2), g, sz);
    }
  };

  uint32_t af[2][4][4], bf[2][8][2];

  const int nkt = P.nkt;
#pragma unroll
  for (int s = 0; s < STAGES - 1; s++) {
    if (s < nkt) issue(s);
    CP_COMMIT();
  }

  for (int kt = 0; kt < nkt; kt++) {
    asm volatile("cp.async.wait_group %0;\n" :: "n"(STAGES - 2) : "memory");
    __syncthreads();
    int buf = kt % STAGES;
    uint32_t sst = sbase + buf * STAGE_BYTES;

    auto lfrag = [&](int ks, int sl) {
      uint32_t ka = sst + aB + (uint32_t)(ks * 32);
#pragma unroll
      for (int tm = 0; tm < 4; tm++) {
        LDSM_X4(af[sl][tm][0], af[sl][tm][1], af[sl][tm][2], af[sl][tm][3],
                ka + tm * 2304u);
      }
      uint32_t kb = sst + SA_BYTES + bB + (uint32_t)(ks * 32);
#pragma unroll
      for (int pr = 0; pr < 4; pr++) {
        LDSM_X4(bf[sl][2 * pr][0], bf[sl][2 * pr][1],
                bf[sl][2 * pr + 1][0], bf[sl][2 * pr + 1][1],
                kb + pr * 2304u);
      }
    };
    auto domma = [&](int sl) {
#pragma unroll
      for (int tm = 0; tm < 4; tm++)
#pragma unroll
        for (int tn = 0; tn < 8; tn++) {
          asm volatile(
              "mma.sync.aligned.m16n8k16.row.col.f32.f16.f16.f32 "
              "{%0,%1,%2,%3}, {%4,%5,%6,%7}, {%8,%9}, {%0,%1,%2,%3};\n"
              : "+f"(acc[tm][tn][0]), "+f"(acc[tm][tn][1]),
                "+f"(acc[tm][tn][2]), "+f"(acc[tm][tn][3])
              : "r"(af[sl][tm][0]), "r"(af[sl][tm][1]),
                "r"(af[sl][tm][2]), "r"(af[sl][tm][3]),
                "r"(bf[sl][tn][0]), "r"(bf[sl][tn][1]));
        }
    };

    lfrag(0, 0);
    if (kt + STAGES - 1 < nkt) issue(kt + STAGES - 1);
    CP_COMMIT();
#pragma unroll
    for (int ks = 0; ks < 4; ks++) {
      if (ks < 3) lfrag(ks + 1, (ks + 1) & 1);
      domma(ks & 1);
    }
  }

  // ---- epilogue ----
#pragma unroll
  for (int tn = 0; tn < 8; tn++) {
    int c0 = n0 + wn * 64 + tn * 8 + 2 * tig;
    if (P.midC && c0 >= 2048) {
      int cm = c0 - 2048;
      if (cm < 100) {
        float b0 = P.midBias[cm], b1 = P.midBias[cm + 1];
#pragma unroll
        for (int tm = 0; tm < 4; tm++) {
          int r0 = m0 + wm * 64 + tm * 16 + gid;
#pragma unroll
          for (int h = 0; h < 2; h++) {
            int r = r0 + h * 8;
            float vx = fmaxf(acc[tm][tn][h * 2] + b0, 0.f);
            float vy = fmaxf(acc[tm][tn][h * 2 + 1] + b1, 0.f);
            *(__half2*)(P.midC + (size_t)r * 128 + cm) = __floats2half2_rn(vx, vy);
          }
        }
      }
      continue;
    }
    if (c0 >= P.N) continue;
    float b0 = P.bias1[c0], b1 = P.bias1[c0 + 1];
    if (P.bias2) { b0 += P.bias2[c0]; b1 += P.bias2[c0 + 1]; }
#pragma unroll
    for (int tm = 0; tm < 4; tm++) {
      int r0 = m0 + wm * 64 + tm * 16 + gid;
#pragma unroll
      for (int h = 0; h < 2; h++) {
        int r = r0 + h * 8;
        float vx = acc[tm][tn][h * 2] + b0;
        float vy = acc[tm][tn][h * 2 + 1] + b1;
        if (P.addC) {
          float2 ad = *(const float2*)(P.addC + (size_t)r * P.addld + c0);
          vx += ad.x; vy += ad.y;
        }
        if (P.act == 2) { vx = tanhf(vx); vy = tanhf(vy); }
        if (P.C1)
          *(float2*)(P.C1 + (size_t)r * P.ldc1 + c0) = make_float2(vx, vy);
        if (P.C2)
          *(__half2*)(P.C2 + (size_t)r * P.ldc2 + c0) = __floats2half2_rn(vx, vy);
      }
    }
  }
}

// ---------------- host --------------------------------------------------------
static void launch_gemm(GP p, const GP* q, int gx, int gy) {
  GP qq = q ? *q : p;
  if (!q) p.gxMain = gx + 1024;  // never select q
  gemm_k<<<dim3(gx + (q ? 2 : 0), gy, 1), NT, SMEM_BYTES>>>(p, qq);
}

extern "C" void kernel_launch(void* const* d_in, const int* in_sizes, int n_in,
                              void* d_out, int out_size) {
  (void)in_sizes; (void)n_in; (void)out_size;
  const float* input  = (const float*)d_in[0];
  const float* hidden = (const float*)d_in[1];
  const float* prevh  = (const float*)d_in[2];
  const float* cell   = (const float*)d_in[3];
  const float* W_ch2  = (const float*)d_in[4];
  const float* b_ch2  = (const float*)d_in[5];
  const float* W_cm2  = (const float*)d_in[6];
  const float* b_cm2  = (const float*)d_in[7];
  const float* W_mo   = (const float*)d_in[8];
  const float* b_mo   = (const float*)d_in[9];
  const float* W_ci   = (const float*)d_in[10];
  const float* b_ci   = (const float*)d_in[11];
  const float* W_ch   = (const float*)d_in[12];
  const float* b_ch   = (const float*)d_in[13];
  const float* W_fc   = (const float*)d_in[14];
  const float* b_fc   = (const float*)d_in[15];
  const float* bias   = (const float*)d_in[16];

  float* out_p = (float*)d_out;                 // [4096,256]
  float* nh_p  = out_p + (size_t)4096 * 256;    // new_hidden
  float* nc_p  = nh_p + (size_t)4096 * 2048;    // new_cell
  float* nph_p = nc_p + (size_t)4096 * 2048;    // new_prev_hidden (= h_proj)

  __half *concat_p, *Wcomb_p, *Wmo_p, *Wci_p, *Wch_p, *Wfc_p;
  __half *nhr_p, *lcr_p, *midr_p;
  cudaGetSymbolAddress((void**)&concat_p, g_concat);
  cudaGetSymbolAddress((void**)&Wcomb_p, g_Wcomb);
  cudaGetSymbolAddress((void**)&Wmo_p, g_Wmo);
  cudaGetSymbolAddress((void**)&Wci_p, g_Wci);
  cudaGetSymbolAddress((void**)&Wch_p, g_Wch);
  cudaGetSymbolAddress((void**)&Wfc_p, g_Wfc);
  cudaGetSymbolAddress((void**)&nhr_p, g_nhr);
  cudaGetSymbolAddress((void**)&lcr_p, g_lcr);
  cudaGetSymbolAddress((void**)&midr_p, g_midr);

  cudaFuncSetAttribute(gemm_k, cudaFuncAttributeMaxDynamicSharedMemorySize,
                       SMEM_BYTES);

  // L0, L1: preprocessing (fp32 -> fp16)
  prep_weights<<<1024, 512>>>(W_ch2, W_cm2, W_mo, W_ci, W_ch, W_fc);
  prep_concat<<<1024, 512>>>(input, hidden, prevh, cell);

  // L2: G1+G2 fused: [new_hidden | mid] = concat @ [Wch2;Wcm2]^T
  {
    GP p{};
    p.N = 2148; p.Ktot = 7168; p.lda = 7168; p.ldb = 7168;
    p.A = concat_p; p.B = Wcomb_p; p.bias1 = b_ch2;
    p.C1 = nh_p; p.ldc1 = 2048; p.C2 = nhr_p; p.ldc2 = 2048;
    p.midC = midr_p; p.midBias = b_cm2;
    p.nkt = 112;
    launch_gemm(p, nullptr, 17, 32);
  }
  // L3: G4 (h_proj) + G3 (out) merged in one grid
  {
    GP p{};
    p.N = 2048; p.Ktot = 2048; p.lda = 2048; p.ldb = 2048;
    p.A = nhr_p; p.B = Wch_p; p.bias1 = b_ch;
    p.C1 = nph_p; p.ldc1 = 2048;
    p.nkt = 32; p.gxMain = 16;
    GP q{};
    q.N = 256; q.Ktot = 128; q.lda = 128; q.ldb = 128;
    q.A = midr_p; q.B = Wmo_p; q.bias1 = b_mo;
    q.C1 = out_p; q.ldc1 = 256;
    q.nkt = 2; q.gxMain = 16;
    launch_gemm(p, &q, 16, 32);
  }
  // L4: G5  lc = input @ W_ci^T + b_ci + bias + h_proj  (fp16->lcr)
  {
    GP p{};
    p.N = 2048; p.Ktot = 1024; p.lda = 7168; p.ldb = 1024;
    p.A = concat_p;  // first 1024 halves per row = fp16 input
    p.B = Wci_p; p.bias1 = b_ci; p.bias2 = bias;
    p.addC = nph_p; p.addld = 2048;
    p.C2 = lcr_p; p.ldc2 = 2048;
    p.nkt = 16;
    launch_gemm(p, nullptr, 16, 32);
  }
  // L5: G6  new_cell = tanh(lc @ W_fc^T + b_fc)   <- ncu capture target
  {
    GP p{};
    p.N = 2048; p.Ktot = 2048; p.lda = 2048; p.ldb = 2048;
    p.A = lcr_p; p.B = Wfc_p; p.bias1 = b_fc;
    p.C1 = nc_p; p.ldc1 = 2048; p.act = 2;
    p.nkt = 32;
    launch_gemm(p, nullptr, 16, 32);
  }
}

// round 9
// speedup vs baseline: 2.8345x; 1.2597x over previous
#include <cuda_runtime.h>
#include <cuda.h>
#include <cuda_fp16.h>
#include <cstdint>
#include <math.h>

#define NT 128
#define STAGES 3
#define A_BYTES 16384            // 128 rows x 128B
#define STAGE_BYTES 32768
#define SMEM_BYTES (1024 + STAGES * STAGE_BYTES)   // 99328 -> 2 CTAs/SM

// ---------------- scratch -----------------------------------------------------
__device__ __align__(16) __half g_concat[(size_t)4096 * 7168];
__device__ __align__(16) __half g_Wcomb[(size_t)2304 * 7168]; // [Wch2;Wcm2;zeros]
__device__ __align__(16) __half g_Wmo[(size_t)256 * 128];
__device__ __align__(16) __half g_Wci[(size_t)2048 * 1024];
__device__ __align__(16) __half g_Wch[(size_t)2048 * 2048];
__device__ __align__(16) __half g_Wfc[(size_t)2048 * 2048];
__device__ __align__(16) __half g_nhr[(size_t)4096 * 2048];
__device__ __align__(16) __half g_lcr[(size_t)4096 * 2048];
__device__ __align__(16) __half g_midr[(size_t)4096 * 128];

// ---------------- asm helpers -------------------------------------------------
#define LDSM_X4(r0, r1, r2, r3, addr) \
  asm volatile("ldmatrix.sync.aligned.m8n8.x4.shared.b16 {%0,%1,%2,%3}, [%4];" \
               : "=r"(r0), "=r"(r1), "=r"(r2), "=r"(r3) : "r"(addr))
#define MBAR_INIT(addr, cnt) \
  asm volatile("mbarrier.init.shared.b64 [%0], %1;" :: "r"(addr), "r"(cnt) : "memory")
#define MBAR_EXPECT_TX(addr, bytes) \
  asm volatile("mbarrier.arrive.expect_tx.shared.b64 _, [%0], %1;" \
               :: "r"(addr), "r"(bytes) : "memory")
#define MBAR_ARRIVE(addr) \
  asm volatile("mbarrier.arrive.shared.b64 _, [%0];" :: "r"(addr) : "memory")
#define MBAR_WAIT(addr, ph) do {                                              \
  uint32_t _m = (addr), _p = (uint32_t)(ph), _d;                              \
  asm volatile("{\n\t.reg .pred p;\n\t"                                       \
    "mbarrier.try_wait.parity.acquire.cta.shared::cta.b64 p, [%1], %2;\n\t"   \
    "selp.b32 %0, 1, 0, p;\n\t}" : "=r"(_d) : "r"(_m), "r"(_p) : "memory");   \
  if (!_d) {                                                                  \
    asm volatile("{\n\t.reg .pred P1;\n\tWL_%=:\n\t"                          \
      "mbarrier.try_wait.parity.acquire.cta.shared::cta.b64 P1, [%0], %1, 0x989680;\n\t" \
      "@P1 bra.uni WD_%=;\n\tbra.uni WL_%=;\n\tWD_%=:\n\t}"                   \
      :: "r"(_m), "r"(_p) : "memory");                                        \
  }                                                                           \
} while (0)
#define TMA2D(saddr, tmap, cx, cy, mbar) \
  asm volatile("cp.async.bulk.tensor.2d.shared::cta.global.tile.mbarrier::complete_tx::bytes " \
               "[%0], [%1, {%2, %3}], [%4];" \
               :: "r"(saddr), "l"(tmap), "r"(cx), "r"(cy), "r"(mbar) : "memory")

// ---------------- preprocessing -----------------------------------------------
__device__ __forceinline__ void cvt_arr(__half* __restrict__ dst,
                                        const float* __restrict__ src, int n8) {
  int stride = gridDim.x * blockDim.x;
  int i0 = blockIdx.x * blockDim.x + threadIdx.x;
  for (int i = i0; i < n8; i += 4 * stride) {
#pragma unroll
    for (int j = 0; j < 4; j++) {
      int k = i + j * stride;
      if (k < n8) {
        float4 a = ((const float4*)src)[2 * k];
        float4 b = ((const float4*)src)[2 * k + 1];
        __half2 h0 = __floats2half2_rn(a.x, a.y);
        __half2 h1 = __floats2half2_rn(a.z, a.w);
        __half2 h2 = __floats2half2_rn(b.x, b.y);
        __half2 h3 = __floats2half2_rn(b.z, b.w);
        uint4 o;
        o.x = *(const uint32_t*)&h0; o.y = *(const uint32_t*)&h1;
        o.z = *(const uint32_t*)&h2; o.w = *(const uint32_t*)&h3;
        ((uint4*)dst)[k] = o;
      }
    }
  }
}

__global__ void prep_weights(const float* W_ch2, const float* W_cm2,
                             const float* W_mo, const float* W_ci,
                             const float* W_ch, const float* W_fc) {
  cvt_arr(g_Wcomb, W_ch2, (2048 * 7168) / 8);
  cvt_arr(g_Wcomb + (size_t)2048 * 7168, W_cm2, (100 * 7168) / 8);
  cvt_arr(g_Wci, W_ci, (2048 * 1024) / 8);
  cvt_arr(g_Wch, W_ch, (2048 * 2048) / 8);
  cvt_arr(g_Wfc, W_fc, (2048 * 2048) / 8);
  int stride = gridDim.x * blockDim.x;
  // zero-fill Wcomb pad rows 2148..2303 (TMA reads them)
  uint4* padp = (uint4*)(g_Wcomb + (size_t)2148 * 7168);
  int npad = (156 * 7168) / 8;
  uint4 z = make_uint4(0, 0, 0, 0);
  for (int i = blockIdx.x * blockDim.x + threadIdx.x; i < npad; i += stride)
    padp[i] = z;
  for (int i = blockIdx.x * blockDim.x + threadIdx.x; i < 256 * 128; i += stride) {
    int r = i >> 7, c = i & 127;
    g_Wmo[i] = (c < 100) ? __float2half_rn(W_mo[r * 100 + c]) : __half(0.f);
  }
}

__global__ void prep_concat(const float* input, const float* hidden,
                            const float* prevh, const float* cell) {
  const int n8 = 4096 * 896;
  int stride = gridDim.x * blockDim.x;
  int i0 = blockIdx.x * blockDim.x + threadIdx.x;
  for (int i = i0; i < n8; i += 4 * stride) {
#pragma unroll
    for (int j = 0; j < 4; j++) {
      int k = i + j * stride;
      if (k < n8) {
        int r = k / 896;
        int c = (k - r * 896) << 3;
        const float* s;
        if (c < 1024)      s = input + (size_t)r * 1024 + c;
        else if (c < 3072) s = hidden + (size_t)r * 2048 + (c - 1024);
        else if (c < 5120) s = prevh + (size_t)r * 2048 + (c - 3072);
        else               s = cell + (size_t)r * 2048 + (c - 5120);
        float4 a = ((const float4*)s)[0];
        float4 b = ((const float4*)s)[1];
        __half2 h0 = __floats2half2_rn(a.x, a.y);
        __half2 h1 = __floats2half2_rn(a.z, a.w);
        __half2 h2 = __floats2half2_rn(b.x, b.y);
        __half2 h3 = __floats2half2_rn(b.z, b.w);
        uint4 o;
        o.x = *(const uint32_t*)&h0; o.y = *(const uint32_t*)&h1;
        o.z = *(const uint32_t*)&h2; o.w = *(const uint32_t*)&h3;
        ((uint4*)g_concat)[k] = o;
      }
    }
  }
}

// ---------------- main GEMM (fp16 m16n8k16, TMA + mbarrier pipeline) ----------
struct GP {
  int N;                   // logical N (cols)
  const float* bias1;
  const float* bias2;
  const float* addC; int addld;
  float* C1; int ldc1;
  __half* C2; int ldc2;
  __half* midC;            // fused-mid output (cols >= 2048), pitch 128
  const float* midBias;
  int act;                 // 0 none, 2 tanh
  int nkt;
  int gxMain;              // bx >= gxMain -> secondary problem
};

__global__ __launch_bounds__(NT, 2)
void gemm_k(const __grid_constant__ CUtensorMap tmA,
            const __grid_constant__ CUtensorMap tmB,
            const __grid_constant__ CUtensorMap tmA2,
            const __grid_constant__ CUtensorMap tmB2,
            GP p, GP q) {
  extern __shared__ __align__(1024) uint32_t sm[];
  const uint32_t sb = (uint32_t)__cvta_generic_to_shared(sm);

  const bool useQ = ((int)blockIdx.x >= p.gxMain);
  const GP P = useQ ? q : p;
  const CUtensorMap* tA = useQ ? &tmA2 : &tmA;
  const CUtensorMap* tB = useQ ? &tmB2 : &tmB;
  const int bx = useQ ? ((int)blockIdx.x - p.gxMain) : (int)blockIdx.x;

  const int tid  = threadIdx.x;
  const int lane = tid & 31;
  const int warp = tid >> 5;
  const int wm   = warp >> 1;    // 0..1 -> 64-row slice
  const int wn   = warp & 1;     // 0..1 -> 64-col slice
  const int gid  = lane >> 2;
  const int tig  = lane & 3;

  const int m0 = blockIdx.y * 128;
  const int n0 = bx * 128;
  const int nkt = P.nkt;

  // barriers: full[s] @ sb + s*8 (count 1), empty[s] @ sb+64+s*8 (count 4)
  if (tid == 0) {
#pragma unroll
    for (int s = 0; s < STAGES; s++) {
      MBAR_INIT(sb + s * 8, 1);
      MBAR_INIT(sb + 64 + s * 8, 4);
    }
  }
  __syncthreads();

  // SW128-swizzled per-lane LDSM bases
  const int arow = wm * 64 + (lane & 15);          // + tm*16
  const int r7a = arow & 7;
  const int hiA = lane >> 4;                       // 0/1 -> k-halves chunk
  const int brow = wn * 64 + (lane & 7) + ((lane >> 4) << 3);  // + pr*16
  const int r7b = lane & 7;
  const int hiB = (lane >> 3) & 1;

  float acc[4][8][4];
#pragma unroll
  for (int a = 0; a < 4; a++)
#pragma unroll
    for (int b = 0; b < 8; b++)
#pragma unroll
      for (int c = 0; c < 4; c++) acc[a][b][c] = 0.f;

  auto produce = [&](int kti) {
    if (kti >= nkt) return;
    int buf = kti % STAGES;
    int rnd = kti / STAGES;
    MBAR_WAIT(sb + 64 + buf * 8, (rnd + 1) & 1);   // wait consumers released
    uint32_t fb = sb + buf * 8;
    MBAR_EXPECT_TX(fb, STAGE_BYTES);
    uint32_t dst = sb + 1024 + buf * STAGE_BYTES;
    int k0 = kti * 64;
    TMA2D(dst, tA, k0, m0, fb);
    TMA2D(dst + A_BYTES, tB, k0, n0, fb);
  };

  if (tid == 0) { produce(0); produce(1); }

  uint32_t af[2][4][4], bf[2][8][2];

  for (int kt = 0; kt < nkt; kt++) {
    if (tid == 0) produce(kt + STAGES - 1);
    int buf = kt % STAGES;
    MBAR_WAIT(sb + buf * 8, (kt / STAGES) & 1);
    uint32_t stA = sb + 1024 + buf * STAGE_BYTES;
    uint32_t stB = stA + A_BYTES;

    auto lfrag = [&](int ks, int sl) {
      uint32_t ca = (uint32_t)(((ks * 2 + hiA) ^ r7a) << 4);
#pragma unroll
      for (int tm = 0; tm < 4; tm++) {
        uint32_t ka = stA + (uint32_t)((arow + tm * 16) << 7) + ca;
        LDSM_X4(af[sl][tm][0], af[sl][tm][1], af[sl][tm][2], af[sl][tm][3], ka);
      }
      uint32_t cb = (uint32_t)(((ks * 2 + hiB) ^ r7b) << 4);
#pragma unroll
      for (int pr = 0; pr < 4; pr++) {
        uint32_t kb = stB + (uint32_t)((brow + pr * 16) << 7) + cb;
        LDSM_X4(bf[sl][2 * pr][0], bf[sl][2 * pr][1],
                bf[sl][2 * pr + 1][0], bf[sl][2 * pr + 1][1], kb);
      }
    };
    auto domma = [&](int sl) {
#pragma unroll
      for (int tm = 0; tm < 4; tm++)
#pragma unroll
        for (int tn = 0; tn < 8; tn++) {
          asm volatile(
              "mma.sync.aligned.m16n8k16.row.col.f32.f16.f16.f32 "
              "{%0,%1,%2,%3}, {%4,%5,%6,%7}, {%8,%9}, {%0,%1,%2,%3};\n"
              : "+f"(acc[tm][tn][0]), "+f"(acc[tm][tn][1]),
                "+f"(acc[tm][tn][2]), "+f"(acc[tm][tn][3])
              : "r"(af[sl][tm][0]), "r"(af[sl][tm][1]),
                "r"(af[sl][tm][2]), "r"(af[sl][tm][3]),
                "r"(bf[sl][tn][0]), "r"(bf[sl][tn][1]));
        }
    };

    lfrag(0, 0);
#pragma unroll
    for (int ks = 0; ks < 4; ks++) {
      if (ks < 3) lfrag(ks + 1, (ks + 1) & 1);
      domma(ks & 1);
    }
    if (lane == 0) MBAR_ARRIVE(sb + 64 + buf * 8);
  }

  // ---- epilogue ----
#pragma unroll
  for (int tn = 0; tn < 8; tn++) {
    int c0 = n0 + wn * 64 + tn * 8 + 2 * tig;
    if (P.midC && c0 >= 2048) {
      int cm = c0 - 2048;
      if (cm < 100) {
        float b0 = P.midBias[cm], b1 = P.midBias[cm + 1];
#pragma unroll
        for (int tm = 0; tm < 4; tm++) {
          int r0 = m0 + wm * 64 + tm * 16 + gid;
#pragma unroll
          for (int h = 0; h < 2; h++) {
            int r = r0 + h * 8;
            float vx = fmaxf(acc[tm][tn][h * 2] + b0, 0.f);
            float vy = fmaxf(acc[tm][tn][h * 2 + 1] + b1, 0.f);
            *(__half2*)(P.midC + (size_t)r * 128 + cm) = __floats2half2_rn(vx, vy);
          }
        }
      }
      continue;
    }
    if (c0 >= P.N) continue;
    float b0 = P.bias1[c0], b1 = P.bias1[c0 + 1];
    if (P.bias2) { b0 += P.bias2[c0]; b1 += P.bias2[c0 + 1]; }
#pragma unroll
    for (int tm = 0; tm < 4; tm++) {
      int r0 = m0 + wm * 64 + tm * 16 + gid;
#pragma unroll
      for (int h = 0; h < 2; h++) {
        int r = r0 + h * 8;
        float vx = acc[tm][tn][h * 2] + b0;
        float vy = acc[tm][tn][h * 2 + 1] + b1;
        if (P.addC) {
          float2 ad = *(const float2*)(P.addC + (size_t)r * P.addld + c0);
          vx += ad.x; vy += ad.y;
        }
        if (P.act == 2) { vx = tanhf(vx); vy = tanhf(vy); }
        if (P.C1)
          *(float2*)(P.C1 + (size_t)r * P.ldc1 + c0) = make_float2(vx, vy);
        if (P.C2)
          *(__half2*)(P.C2 + (size_t)r * P.ldc2 + c0) = __floats2half2_rn(vx, vy);
      }
    }
  }
}

// ---------------- host --------------------------------------------------------
typedef CUresult (*EncFn)(CUtensorMap*, CUtensorMapDataType, cuuint32_t, void*,
                          const cuuint64_t*, const cuuint64_t*, const cuuint32_t*,
                          const cuuint32_t*, CUtensorMapInterleave, CUtensorMapSwizzle,
                          CUtensorMapL2promotion, CUtensorMapFloatOOBfill);
static EncFn get_enc() {
  static void* fp = nullptr;
  if (!fp) {
    cudaDriverEntryPointQueryResult qr;
    cudaGetDriverEntryPoint("cuTensorMapEncodeTiled", &fp, cudaEnableDefault, &qr);
  }
  return (EncFn)fp;
}
static void enc2d(CUtensorMap* tm, const void* ptr, uint64_t d0, uint64_t d1,
                  uint64_t strideB) {
  cuuint64_t dims[2] = {d0, d1};
  cuuint64_t strides[1] = {strideB};
  cuuint32_t box[2] = {64, 128};
  cuuint32_t es[2] = {1, 1};
  get_enc()(tm, CU_TENSOR_MAP_DATA_TYPE_FLOAT16, 2, (void*)ptr, dims, strides,
            box, es, CU_TENSOR_MAP_INTERLEAVE_NONE, CU_TENSOR_MAP_SWIZZLE_128B,
            CU_TENSOR_MAP_L2_PROMOTION_L2_128B, CU_TENSOR_MAP_FLOAT_OOB_FILL_NONE);
}

static void launch_gemm(const CUtensorMap& a, const CUtensorMap& b,
                        const CUtensorMap& a2, const CUtensorMap& b2,
                        GP p, const GP* q, int gx, int gy) {
  GP qq = q ? *q : p;
  if (!q) p.gxMain = gx + 1024;
  gemm_k<<<dim3(gx + (q ? 2 : 0), gy, 1), NT, SMEM_BYTES>>>(a, b, a2, b2, p, qq);
}

extern "C" void kernel_launch(void* const* d_in, const int* in_sizes, int n_in,
                              void* d_out, int out_size) {
  (void)in_sizes; (void)n_in; (void)out_size;
  const float* input  = (const float*)d_in[0];
  const float* hidden = (const float*)d_in[1];
  const float* prevh  = (const float*)d_in[2];
  const float* cell   = (const float*)d_in[3];
  const float* W_ch2  = (const float*)d_in[4];
  const float* b_ch2  = (const float*)d_in[5];
  const float* W_cm2  = (const float*)d_in[6];
  const float* b_cm2  = (const float*)d_in[7];
  const float* W_mo   = (const float*)d_in[8];
  const float* b_mo   = (const float*)d_in[9];
  const float* W_ci   = (const float*)d_in[10];
  const float* b_ci   = (const float*)d_in[11];
  const float* W_ch   = (const float*)d_in[12];
  const float* b_ch   = (const float*)d_in[13];
  const float* W_fc   = (const float*)d_in[14];
  const float* b_fc   = (const float*)d_in[15];
  const float* bias   = (const float*)d_in[16];

  float* out_p = (float*)d_out;                 // [4096,256]
  float* nh_p  = out_p + (size_t)4096 * 256;    // new_hidden
  float* nc_p  = nh_p + (size_t)4096 * 2048;    // new_cell
  float* nph_p = nc_p + (size_t)4096 * 2048;    // new_prev_hidden (= h_proj)

  __half *concat_p, *Wcomb_p, *Wmo_p, *Wci_p, *Wch_p, *Wfc_p;
  __half *nhr_p, *lcr_p, *midr_p;
  cudaGetSymbolAddress((void**)&concat_p, g_concat);
  cudaGetSymbolAddress((void**)&Wcomb_p, g_Wcomb);
  cudaGetSymbolAddress((void**)&Wmo_p, g_Wmo);
  cudaGetSymbolAddress((void**)&Wci_p, g_Wci);
  cudaGetSymbolAddress((void**)&Wch_p, g_Wch);
  cudaGetSymbolAddress((void**)&Wfc_p, g_Wfc);
  cudaGetSymbolAddress((void**)&nhr_p, g_nhr);
  cudaGetSymbolAddress((void**)&lcr_p, g_lcr);
  cudaGetSymbolAddress((void**)&midr_p, g_midr);

  cudaFuncSetAttribute(gemm_k, cudaFuncAttributeMaxDynamicSharedMemorySize,
                       SMEM_BYTES);

  // L0, L1: preprocessing (fp32 -> fp16)
  prep_weights<<<1024, 512>>>(W_ch2, W_cm2, W_mo, W_ci, W_ch, W_fc);
  prep_concat<<<1024, 512>>>(input, hidden, prevh, cell);

  CUtensorMap tA, tB, tA2, tB2;

  // L2: G1+G2 fused: [new_hidden | mid] = concat @ [Wch2;Wcm2]^T
  {
    enc2d(&tA, concat_p, 7168, 4096, 7168ull * 2);
    enc2d(&tB, Wcomb_p, 7168, 2304, 7168ull * 2);
    GP p{};
    p.N = 2148; p.bias1 = b_ch2;
    p.C1 = nh_p; p.ldc1 = 2048; p.C2 = nhr_p; p.ldc2 = 2048;
    p.midC = midr_p; p.midBias = b_cm2;
    p.nkt = 112;
    launch_gemm(tA, tB, tA, tB, p, nullptr, 17, 32);
  }
  // L3: G4 (h_proj) + G3 (out) merged
  {
    enc2d(&tA, nhr_p, 2048, 4096, 2048ull * 2);
    enc2d(&tB, Wch_p, 2048, 2048, 2048ull * 2);
    enc2d(&tA2, midr_p, 128, 4096, 128ull * 2);
    enc2d(&tB2, Wmo_p, 128, 256, 128ull * 2);
    GP p{};
    p.N = 2048; p.bias1 = b_ch;
    p.C1 = nph_p; p.ldc1 = 2048;
    p.nkt = 32; p.gxMain = 16;
    GP q{};
    q.N = 256; q.bias1 = b_mo;
    q.C1 = out_p; q.ldc1 = 256;
    q.nkt = 2; q.gxMain = 16;
    launch_gemm(tA, tB, tA2, tB2, p, &q, 16, 32);
  }
  // L4: G5  lc = input @ W_ci^T + b_ci + bias + h_proj  (fp16->lcr)
  {
    enc2d(&tA, concat_p, 7168, 4096, 7168ull * 2);  // k < 1024 = input cols
    enc2d(&tB, Wci_p, 1024, 2048, 1024ull * 2);
    GP p{};
    p.N = 2048; p.bias1 = b_ci; p.bias2 = bias;
    p.addC = nph_p; p.addld = 2048;
    p.C2 = lcr_p; p.ldc2 = 2048;
    p.nkt = 16;
    launch_gemm(tA, tB, tA, tB, p, nullptr, 16, 32);
  }
  // L5: G6  new_cell = tanh(lc @ W_fc^T + b_fc)   <- ncu capture target
  {
    enc2d(&tA, lcr_p, 2048, 4096, 2048ull * 2);
    enc2d(&tB, Wfc_p, 2048, 2048, 2048ull * 2);
    GP p{};
    p.N = 2048; p.bias1 = b_fc;
    p.C1 = nc_p; p.ldc1 = 2048; p.act = 2;
    p.nkt = 32;
    launch_gemm(tA, tB, tA, tB, p, nullptr, 16, 32);
  }
}